// round 13
// baseline (speedup 1.0000x reference)
#include <cuda_runtime.h>
#include <cuda_bf16.h>

// GraphSAGE 2-layer, N=100000, E=1600000, D=128.
// R13: warp-specialized fused layer kernel — warps 0-15 run the R10 GEMM
// (fma roofline), warps 16-31 aggregate the NEXT tile's neighbor means
// concurrently (L2-bound). One bar.sync(1024) per tile. Per-layer time
// collapses from agg+gemm to ~max(agg, gemm).

#define N_NODES 100000
#define N_EDGES 1600000
#define DFEAT   128
#define SCAN_BLK 1024
#define MAX_SCAN_BLOCKS ((N_NODES + SCAN_BLK - 1) / SCAN_BLK + 1)

// ---------------- scratch (device globals; no allocation allowed) ----------
__device__ int   g_is_i64;
__device__ int   g_src[N_EDGES];
__device__ int   g_dst[N_EDGES];
__device__ int   g_cursor[N_NODES];
__device__ int   g_rowptr[N_NODES + 1];
__device__ int   g_col[N_EDGES];
__device__ int   g_bsum[MAX_SCAN_BLOCKS];
__device__ float g_mean[(size_t)N_NODES * DFEAT];
__device__ float g_h[(size_t)N_NODES * DFEAT];

// ---------------- small helpers -------------------------------------------
__device__ __forceinline__ unsigned long long dup_f32x2(float a) {
    unsigned long long r;
    asm("mov.b64 %0, {%1, %1};" : "=l"(r) : "f"(a));
    return r;
}
__device__ __forceinline__ void unpack_f32x2(unsigned long long v, float& lo, float& hi) {
    asm("mov.b64 {%0, %1}, %2;" : "=f"(lo), "=f"(hi) : "l"(v));
}
#define FFMA2(d, a, b, c) \
    asm("fma.rn.f32x2 %0, %1, %2, %3;" : "=l"(d) : "l"(a), "l"(b), "l"(c))
#define BAR_GEMM()  asm volatile("bar.sync 3, 512;" ::: "memory")
#define BAR_TILE()  asm volatile("bar.sync 4, 1024;" ::: "memory")

__device__ __forceinline__ int clamp_node(int v, int n) {
    unsigned u = (unsigned)v;
    return (u < (unsigned)n) ? v : 0;
}

// ---------------- edge dtype detect + (extract + degree count) -------------
__global__ void detect_kernel(const int* __restrict__ ew) {
    int flag = 0;
    for (int i = 1; i < 128; i += 2) flag |= ew[i];
    g_is_i64 = (flag == 0) ? 1 : 0;
}

__global__ void convert_count_kernel(const int* __restrict__ ew, int nedges, int nnodes) {
    int e = blockIdx.x * blockDim.x + threadIdx.x;
    if (e >= nedges) return;
    int s, d;
    if (g_is_i64) {
        s = ew[2 * (size_t)e];
        d = ew[2 * ((size_t)nedges + e)];
    } else {
        s = ew[e];
        d = ew[(size_t)nedges + e];
    }
    s = clamp_node(s, nnodes);
    d = clamp_node(d, nnodes);
    g_src[e] = s;
    g_dst[e] = d;
    atomicAdd(&g_cursor[d], 1);
}

__global__ void zero_int_kernel(int* p, int n) {
    int i = blockIdx.x * blockDim.x + threadIdx.x;
    if (i < n) p[i] = 0;
}

// ---------------- parallel scan: 3 phases ----------------------------------
__global__ void __launch_bounds__(SCAN_BLK)
scan_partial_kernel(int n) {
    __shared__ int warp_sums[32];
    int i = blockIdx.x * SCAN_BLK + threadIdx.x;
    int lane = threadIdx.x & 31;
    int wid = threadIdx.x >> 5;
    int v = (i < n) ? g_cursor[i] : 0;
    int x = v;
#pragma unroll
    for (int o = 1; o < 32; o <<= 1) {
        int y = __shfl_up_sync(0xffffffffu, x, o);
        if (lane >= o) x += y;
    }
    if (lane == 31) warp_sums[wid] = x;
    __syncthreads();
    if (wid == 0) {
        int s = warp_sums[lane];
#pragma unroll
        for (int o = 1; o < 32; o <<= 1) {
            int y = __shfl_up_sync(0xffffffffu, s, o);
            if (lane >= o) s += y;
        }
        warp_sums[lane] = s;
    }
    __syncthreads();
    int base = (wid > 0) ? warp_sums[wid - 1] : 0;
    if (i < n) g_rowptr[i] = base + x - v;
    if (threadIdx.x == SCAN_BLK - 1) g_bsum[blockIdx.x] = base + x;
}

__global__ void __launch_bounds__(SCAN_BLK)
scan_bsums_kernel(int nblocks, int n) {
    __shared__ int warp_sums[32];
    int t = threadIdx.x;
    int lane = t & 31;
    int wid = t >> 5;
    int v = (t < nblocks) ? g_bsum[t] : 0;
    int x = v;
#pragma unroll
    for (int o = 1; o < 32; o <<= 1) {
        int y = __shfl_up_sync(0xffffffffu, x, o);
        if (lane >= o) x += y;
    }
    if (lane == 31) warp_sums[wid] = x;
    __syncthreads();
    if (wid == 0) {
        int s = warp_sums[lane];
#pragma unroll
        for (int o = 1; o < 32; o <<= 1) {
            int y = __shfl_up_sync(0xffffffffu, s, o);
            if (lane >= o) s += y;
        }
        warp_sums[lane] = s;
    }
    __syncthreads();
    int base = (wid > 0) ? warp_sums[wid - 1] : 0;
    if (t < nblocks) g_bsum[t] = base + x - v;
    if (t == SCAN_BLK - 1) g_rowptr[n] = base + x;
}

__global__ void __launch_bounds__(SCAN_BLK)
scan_add_kernel(int n) {
    int i = blockIdx.x * SCAN_BLK + threadIdx.x;
    if (i >= n) return;
    g_rowptr[i] += g_bsum[blockIdx.x];
    g_cursor[i] = 0;
}

__global__ void fill_csr_kernel(int nedges) {
    int e = blockIdx.x * blockDim.x + threadIdx.x;
    if (e >= nedges) return;
    int dst = g_dst[e];
    int pos = g_rowptr[dst] + atomicAdd(&g_cursor[dst], 1);
    g_col[pos] = g_src[e];
}

// ---------------- warp-specialized fused SAGE layer --------------------------
// grid=148 persistent CTAs x 1024 threads.
//   warps  0-15 (tid <  512): GEMM of tile t  (reads g_mean + feat, fma-bound)
//   warps 16-31 (tid >= 512): aggregation of tile t+gridDim (L2-bound)
// One bar.sync(4,1024) per tile orders mean[t+1] writes before its GEMM.
#define W_STRIDE 132
#define GTILE    128
#define LAYER_SMEM (256 * W_STRIDE * 4 + 2 * 32 * 128 * 8)

// aggregate one node's neighbor mean into g_mean (one warp, R10 inner loop)
__device__ __forceinline__ void agg_node(const float* __restrict__ feat,
                                         int nd, int lane, int lane4) {
    int start = g_rowptr[nd];
    int end = g_rowptr[nd + 1];
    float ax = 0.f, ay = 0.f, az = 0.f, aw = 0.f;
    for (int base = start; base < end; base += 32) {
        int m = min(32, end - base);
        int sv = (lane < m) ? g_col[base + lane] : 0;
        int kk = 0;
        for (; kk + 4 <= m; kk += 4) {
            int s0 = __shfl_sync(0xffffffffu, sv, kk);
            int s1 = __shfl_sync(0xffffffffu, sv, kk + 1);
            int s2 = __shfl_sync(0xffffffffu, sv, kk + 2);
            int s3 = __shfl_sync(0xffffffffu, sv, kk + 3);
            float4 v0 = *reinterpret_cast<const float4*>(feat + (size_t)s0 * DFEAT + lane4);
            float4 v1 = *reinterpret_cast<const float4*>(feat + (size_t)s1 * DFEAT + lane4);
            float4 v2 = *reinterpret_cast<const float4*>(feat + (size_t)s2 * DFEAT + lane4);
            float4 v3 = *reinterpret_cast<const float4*>(feat + (size_t)s3 * DFEAT + lane4);
            ax += v0.x + v1.x + v2.x + v3.x;
            ay += v0.y + v1.y + v2.y + v3.y;
            az += v0.z + v1.z + v2.z + v3.z;
            aw += v0.w + v1.w + v2.w + v3.w;
        }
        for (; kk < m; ++kk) {
            int s = __shfl_sync(0xffffffffu, sv, kk);
            float4 v = *reinterpret_cast<const float4*>(feat + (size_t)s * DFEAT + lane4);
            ax += v.x; ay += v.y; az += v.z; aw += v.w;
        }
    }
    float inv = 1.f / fmaxf((float)(end - start), 1.f);
    float4 o;
    o.x = ax * inv; o.y = ay * inv; o.z = az * inv; o.w = aw * inv;
    *reinterpret_cast<float4*>(g_mean + (size_t)nd * DFEAT + lane4) = o;
}

__global__ void __launch_bounds__(1024, 1)
sage_layer_kernel(const float* __restrict__ feat,
                  const float* __restrict__ Wl,
                  const float* __restrict__ Wr,
                  const float* __restrict__ bias,
                  float* __restrict__ out,
                  int nnodes, int relu, int ntiles) {
    extern __shared__ float smem[];
    float* sW = smem;                                                   // 256*132
    unsigned long long* sA2 =
        reinterpret_cast<unsigned long long*>(smem + 256 * W_STRIDE);   // 2*32*128

    int tid = threadIdx.x;
    int lane = tid & 31;

    // Load + transpose weights ONCE per CTA (all 1024 threads).
    for (int idx = tid; idx < 128 * 128; idx += 1024) {
        int j = idx >> 7;
        int k = idx & 127;
        sW[k * W_STRIDE + j] = Wl[idx];
        sW[(k + 128) * W_STRIDE + j] = Wr[idx];
    }

    if (tid < 512) {
        // ======================= GEMM role =======================
        int warp = tid >> 5;
        int j0 = lane * 4;
        int st_node = tid >> 2;           // 0..127
        int st_q = tid & 3;               // 0..3
        int kb = st_q * 8;

        float4 bv = *reinterpret_cast<const float4*>(bias + j0);
        unsigned long long b01, b23;
        asm("mov.b64 %0, {%1, %2};" : "=l"(b01) : "f"(bv.x), "f"(bv.y));
        asm("mov.b64 %0, {%1, %2};" : "=l"(b23) : "f"(bv.z), "f"(bv.w));

        BAR_TILE();   // wait: prologue agg of first tile + sW loaded

        for (int tile = blockIdx.x; tile < ntiles; tile += gridDim.x) {
            int base_node = tile * GTILE;
            int st_gnode = base_node + st_node;
            if (st_gnode >= nnodes) st_gnode = nnodes - 1;
            const float* a0p = g_mean + (size_t)st_gnode * DFEAT + st_q * 8;
            const float* a1p = feat + (size_t)st_gnode * DFEAT + st_q * 8;

            float4 v0 = *reinterpret_cast<const float4*>(a0p);
            float4 v1 = *reinterpret_cast<const float4*>(a0p + 4);

            unsigned long long acc[16];
#pragma unroll
            for (int m = 0; m < 8; ++m) { acc[2 * m] = b01; acc[2 * m + 1] = b23; }

            for (int c = 0; c < 8; ++c) {
                unsigned long long* buf = sA2 + (c & 1) * (32 * 128);
                buf[(kb + 0) * 128 + st_node] = dup_f32x2(v0.x);
                buf[(kb + 1) * 128 + st_node] = dup_f32x2(v0.y);
                buf[(kb + 2) * 128 + st_node] = dup_f32x2(v0.z);
                buf[(kb + 3) * 128 + st_node] = dup_f32x2(v0.w);
                buf[(kb + 4) * 128 + st_node] = dup_f32x2(v1.x);
                buf[(kb + 5) * 128 + st_node] = dup_f32x2(v1.y);
                buf[(kb + 6) * 128 + st_node] = dup_f32x2(v1.z);
                buf[(kb + 7) * 128 + st_node] = dup_f32x2(v1.w);

                if (c + 1 < 8) {
                    int cn = c + 1;
                    const float* ap = (cn < 4) ? a0p : a1p;
                    int koff = (cn & 3) * 32;
                    v0 = *reinterpret_cast<const float4*>(ap + koff);
                    v1 = *reinterpret_cast<const float4*>(ap + koff + 4);
                }
                BAR_GEMM();

                int krow = c * 32;
                const unsigned long long* aw_base = buf + warp * 8;
#pragma unroll 4
                for (int kk = 0; kk < 32; ++kk) {
                    ulonglong2 wv = *reinterpret_cast<const ulonglong2*>(
                        &sW[(krow + kk) * W_STRIDE + j0]);
                    const ulonglong2* ar2 =
                        reinterpret_cast<const ulonglong2*>(aw_base + kk * 128);
                    ulonglong2 a01 = ar2[0];
                    ulonglong2 a23 = ar2[1];
                    ulonglong2 a45 = ar2[2];
                    ulonglong2 a67 = ar2[3];
                    FFMA2(acc[0],  a01.x, wv.x, acc[0]);
                    FFMA2(acc[1],  a01.x, wv.y, acc[1]);
                    FFMA2(acc[2],  a01.y, wv.x, acc[2]);
                    FFMA2(acc[3],  a01.y, wv.y, acc[3]);
                    FFMA2(acc[4],  a23.x, wv.x, acc[4]);
                    FFMA2(acc[5],  a23.x, wv.y, acc[5]);
                    FFMA2(acc[6],  a23.y, wv.x, acc[6]);
                    FFMA2(acc[7],  a23.y, wv.y, acc[7]);
                    FFMA2(acc[8],  a45.x, wv.x, acc[8]);
                    FFMA2(acc[9],  a45.x, wv.y, acc[9]);
                    FFMA2(acc[10], a45.y, wv.x, acc[10]);
                    FFMA2(acc[11], a45.y, wv.y, acc[11]);
                    FFMA2(acc[12], a67.x, wv.x, acc[12]);
                    FFMA2(acc[13], a67.x, wv.y, acc[13]);
                    FFMA2(acc[14], a67.y, wv.x, acc[14]);
                    FFMA2(acc[15], a67.y, wv.y, acc[15]);
                }
            }

            int wnode = base_node + warp * 8;
#pragma unroll
            for (int m = 0; m < 8; ++m) {
                int nd = wnode + m;
                if (nd >= nnodes) break;
                float4 o;
                unpack_f32x2(acc[2 * m], o.x, o.y);
                unpack_f32x2(acc[2 * m + 1], o.z, o.w);
                if (relu) {
                    o.x = fmaxf(o.x, 0.f); o.y = fmaxf(o.y, 0.f);
                    o.z = fmaxf(o.z, 0.f); o.w = fmaxf(o.w, 0.f);
                }
                *reinterpret_cast<float4*>(out + (size_t)nd * DFEAT + j0) = o;
            }
            BAR_TILE();   // mean[tile+grid] now ready; sA2 safe to reuse
        }
    } else {
        // ======================= AGG role =======================
        int aw = (tid - 512) >> 5;        // 0..15
        int lane4 = lane * 4;

        // prologue: aggregate this CTA's first tile
        {
            int tile = blockIdx.x;
            int nbase = tile * GTILE + aw * 8;
#pragma unroll 1
            for (int j = 0; j < 8; ++j) {
                int nd = nbase + j;
                if (nd >= nnodes) break;
                agg_node(feat, nd, lane, lane4);
            }
        }
        BAR_TILE();

        for (int tile = blockIdx.x; tile < ntiles; tile += gridDim.x) {
            int nt = tile + gridDim.x;
            if (nt < ntiles) {
                int nbase = nt * GTILE + aw * 8;
#pragma unroll 1
                for (int j = 0; j < 8; ++j) {
                    int nd = nbase + j;
                    if (nd >= nnodes) break;
                    agg_node(feat, nd, lane, lane4);
                }
            }
            BAR_TILE();
        }
    }
}

// ---------------- launch ----------------------------------------------------
extern "C" void kernel_launch(void* const* d_in, const int* in_sizes, int n_in,
                              void* d_out, int out_size) {
    const float* x   = (const float*)d_in[0];
    const int*   ew  = (const int*)d_in[1];
    const float* Wl1 = (const float*)d_in[2];
    const float* bl1 = (const float*)d_in[3];
    const float* Wr1 = (const float*)d_in[4];
    const float* Wl2 = (const float*)d_in[5];
    const float* bl2 = (const float*)d_in[6];
    const float* Wr2 = (const float*)d_in[7];
    float*       out = (float*)d_out;

    int n = in_sizes[0] / DFEAT;      // 100000
    int e = in_sizes[1] / 2;          // 1600000

    void *p_h_v, *p_cursor_v;
    cudaGetSymbolAddress(&p_h_v, g_h);
    cudaGetSymbolAddress(&p_cursor_v, g_cursor);
    float* p_h = (float*)p_h_v;
    int* p_cursor = (int*)p_cursor_v;

    cudaFuncSetAttribute(sage_layer_kernel,
                         cudaFuncAttributeMaxDynamicSharedMemorySize, LAYER_SMEM);

    int zb = (n + 255) / 256;
    int eb = (e + 255) / 256;
    int sb = (n + SCAN_BLK - 1) / SCAN_BLK;
    int ntiles = (n + GTILE - 1) / GTILE;

    // ---- CSR build ----
    detect_kernel<<<1, 1>>>(ew);
    zero_int_kernel<<<zb, 256>>>(p_cursor, n);
    convert_count_kernel<<<eb, 256>>>(ew, e, n);
    scan_partial_kernel<<<sb, SCAN_BLK>>>(n);
    scan_bsums_kernel<<<1, SCAN_BLK>>>(sb, n);
    scan_add_kernel<<<sb, SCAN_BLK>>>(n);
    fill_csr_kernel<<<eb, 256>>>(e);

    // ---- layer 1 (fused agg-pipeline + GEMM) ----
    sage_layer_kernel<<<148, 1024, LAYER_SMEM>>>(x, Wl1, Wr1, bl1, p_h, n, 1, ntiles);

    // ---- layer 2 ----
    sage_layer_kernel<<<148, 1024, LAYER_SMEM>>>(p_h, Wl2, Wr2, bl2, out, n, 0, ntiles);
}

// round 14
// speedup vs baseline: 1.9310x; 1.9310x over previous
#include <cuda_runtime.h>
#include <cuda_bf16.h>
#include <cstdint>

// GraphSAGE 2-layer, N=100000, E=1600000, D=128.
// R14: GEMM on tensor cores via baseline-PTX mma.sync.m16n8k16.bf16 (+ldmatrix)
// with bf16x3 error compensation (hi*hi + hi*lo + lo*hi) -> rel_err ~1e-5.
// tcgen05 is sm_103a-only and rejected by the compute_103 virtual target;
// mma.sync/ldmatrix are sm_80 baseline and compile. Build/agg = R10 verbatim.

#define N_NODES 100000
#define N_EDGES 1600000
#define DFEAT   128
#define SCAN_BLK 1024
#define MAX_SCAN_BLOCKS ((N_NODES + SCAN_BLK - 1) / SCAN_BLK + 1)

// ---------------- scratch (device globals; no allocation allowed) ----------
__device__ int   g_is_i64;
__device__ int   g_src[N_EDGES];
__device__ int   g_dst[N_EDGES];
__device__ int   g_cursor[N_NODES];
__device__ int   g_rowptr[N_NODES + 1];
__device__ int   g_col[N_EDGES];
__device__ int   g_bsum[MAX_SCAN_BLOCKS];
__device__ float g_mean[(size_t)N_NODES * DFEAT];
__device__ float g_h[(size_t)N_NODES * DFEAT];

// ---------------- helpers ---------------------------------------------------
__device__ __forceinline__ int clamp_node(int v, int n) {
    unsigned u = (unsigned)v;
    return (u < (unsigned)n) ? v : 0;
}
__device__ __forceinline__ uint32_t smem_u32(const void* p) {
    uint32_t a;
    asm("{ .reg .u64 t; cvta.to.shared.u64 t, %1; cvt.u32.u64 %0, t; }"
        : "=r"(a) : "l"(p));
    return a;
}

#define LDMX4(r, addr) \
    asm volatile("ldmatrix.sync.aligned.m8n8.x4.shared.b16 {%0,%1,%2,%3}, [%4];" \
        : "=r"((r)[0]), "=r"((r)[1]), "=r"((r)[2]), "=r"((r)[3]) : "r"(addr))
#define LDMX2(r0, r1, addr) \
    asm volatile("ldmatrix.sync.aligned.m8n8.x2.shared.b16 {%0,%1}, [%2];" \
        : "=r"(r0), "=r"(r1) : "r"(addr))
#define MMA4(d, a, b0_, b1_) \
    asm volatile("mma.sync.aligned.m16n8k16.row.col.f32.bf16.bf16.f32 " \
        "{%0,%1,%2,%3}, {%4,%5,%6,%7}, {%8,%9}, {%0,%1,%2,%3};" \
        : "+f"((d)[0]), "+f"((d)[1]), "+f"((d)[2]), "+f"((d)[3]) \
        : "r"((a)[0]), "r"((a)[1]), "r"((a)[2]), "r"((a)[3]), "r"(b0_), "r"(b1_))

// ---------------- edge dtype detect + (extract + degree count) -------------
__global__ void detect_kernel(const int* __restrict__ ew) {
    int flag = 0;
    for (int i = 1; i < 128; i += 2) flag |= ew[i];
    g_is_i64 = (flag == 0) ? 1 : 0;
}

__global__ void convert_count_kernel(const int* __restrict__ ew, int nedges, int nnodes) {
    int e = blockIdx.x * blockDim.x + threadIdx.x;
    if (e >= nedges) return;
    int s, d;
    if (g_is_i64) {
        s = ew[2 * (size_t)e];
        d = ew[2 * ((size_t)nedges + e)];
    } else {
        s = ew[e];
        d = ew[(size_t)nedges + e];
    }
    s = clamp_node(s, nnodes);
    d = clamp_node(d, nnodes);
    g_src[e] = s;
    g_dst[e] = d;
    atomicAdd(&g_cursor[d], 1);
}

__global__ void zero_int_kernel(int* p, int n) {
    int i = blockIdx.x * blockDim.x + threadIdx.x;
    if (i < n) p[i] = 0;
}

// ---------------- parallel scan: 3 phases ----------------------------------
__global__ void __launch_bounds__(SCAN_BLK)
scan_partial_kernel(int n) {
    __shared__ int warp_sums[32];
    int i = blockIdx.x * SCAN_BLK + threadIdx.x;
    int lane = threadIdx.x & 31;
    int wid = threadIdx.x >> 5;
    int v = (i < n) ? g_cursor[i] : 0;
    int x = v;
#pragma unroll
    for (int o = 1; o < 32; o <<= 1) {
        int y = __shfl_up_sync(0xffffffffu, x, o);
        if (lane >= o) x += y;
    }
    if (lane == 31) warp_sums[wid] = x;
    __syncthreads();
    if (wid == 0) {
        int s = warp_sums[lane];
#pragma unroll
        for (int o = 1; o < 32; o <<= 1) {
            int y = __shfl_up_sync(0xffffffffu, s, o);
            if (lane >= o) s += y;
        }
        warp_sums[lane] = s;
    }
    __syncthreads();
    int base = (wid > 0) ? warp_sums[wid - 1] : 0;
    if (i < n) g_rowptr[i] = base + x - v;
    if (threadIdx.x == SCAN_BLK - 1) g_bsum[blockIdx.x] = base + x;
}

__global__ void __launch_bounds__(SCAN_BLK)
scan_bsums_kernel(int nblocks, int n) {
    __shared__ int warp_sums[32];
    int t = threadIdx.x;
    int lane = t & 31;
    int wid = t >> 5;
    int v = (t < nblocks) ? g_bsum[t] : 0;
    int x = v;
#pragma unroll
    for (int o = 1; o < 32; o <<= 1) {
        int y = __shfl_up_sync(0xffffffffu, x, o);
        if (lane >= o) x += y;
    }
    if (lane == 31) warp_sums[wid] = x;
    __syncthreads();
    if (wid == 0) {
        int s = warp_sums[lane];
#pragma unroll
        for (int o = 1; o < 32; o <<= 1) {
            int y = __shfl_up_sync(0xffffffffu, s, o);
            if (lane >= o) s += y;
        }
        warp_sums[lane] = s;
    }
    __syncthreads();
    int base = (wid > 0) ? warp_sums[wid - 1] : 0;
    if (t < nblocks) g_bsum[t] = base + x - v;
    if (t == SCAN_BLK - 1) g_rowptr[n] = base + x;
}

__global__ void __launch_bounds__(SCAN_BLK)
scan_add_kernel(int n) {
    int i = blockIdx.x * SCAN_BLK + threadIdx.x;
    if (i >= n) return;
    g_rowptr[i] += g_bsum[blockIdx.x];
    g_cursor[i] = 0;
}

__global__ void fill_csr_kernel(int nedges) {
    int e = blockIdx.x * blockDim.x + threadIdx.x;
    if (e >= nedges) return;
    int dst = g_dst[e];
    int pos = g_rowptr[dst] + atomicAdd(&g_cursor[dst], 1);
    g_col[pos] = g_src[e];
}

// ---------------- mean aggregation: one warp per node (R10) -----------------
__global__ void agg_mean_kernel(const float* __restrict__ feat, int nnodes) {
    int gwarp = (blockIdx.x * blockDim.x + threadIdx.x) >> 5;
    int lane = threadIdx.x & 31;
    if (gwarp >= nnodes) return;

    int start = g_rowptr[gwarp];
    int end = g_rowptr[gwarp + 1];
    float ax = 0.f, ay = 0.f, az = 0.f, aw = 0.f;
    int lane4 = lane * 4;

    for (int base = start; base < end; base += 32) {
        int m = min(32, end - base);
        int sv = (lane < m) ? g_col[base + lane] : 0;
        int kk = 0;
        for (; kk + 4 <= m; kk += 4) {
            int s0 = __shfl_sync(0xffffffffu, sv, kk);
            int s1 = __shfl_sync(0xffffffffu, sv, kk + 1);
            int s2 = __shfl_sync(0xffffffffu, sv, kk + 2);
            int s3 = __shfl_sync(0xffffffffu, sv, kk + 3);
            float4 v0 = *reinterpret_cast<const float4*>(feat + (size_t)s0 * DFEAT + lane4);
            float4 v1 = *reinterpret_cast<const float4*>(feat + (size_t)s1 * DFEAT + lane4);
            float4 v2 = *reinterpret_cast<const float4*>(feat + (size_t)s2 * DFEAT + lane4);
            float4 v3 = *reinterpret_cast<const float4*>(feat + (size_t)s3 * DFEAT + lane4);
            ax += v0.x + v1.x + v2.x + v3.x;
            ay += v0.y + v1.y + v2.y + v3.y;
            az += v0.z + v1.z + v2.z + v3.z;
            aw += v0.w + v1.w + v2.w + v3.w;
        }
        for (; kk < m; ++kk) {
            int s = __shfl_sync(0xffffffffu, sv, kk);
            float4 v = *reinterpret_cast<const float4*>(feat + (size_t)s * DFEAT + lane4);
            ax += v.x; ay += v.y; az += v.z; aw += v.w;
        }
    }
    float inv = 1.f / fmaxf((float)(end - start), 1.f);
    float4 o;
    o.x = ax * inv; o.y = ay * inv; o.z = az * inv; o.w = aw * inv;
    *reinterpret_cast<float4*>(g_mean + (size_t)gwarp * DFEAT + lane4) = o;
}

// ---------------- tensor-core SAGE GEMM (bf16x3 mma.sync) --------------------
// out[n][j] = sum_k A[n][k]*B[j][k] + b[j]; A = [mean|feat] (K=256),
// B = [Wl|Wr] rows=j. Persistent grid=148 x 512 threads, 128-node tiles.
// Warp w: m-pair mi2=w&3 (rows mi2*32..+31), n-group ng=w>>2 (j ng*32..+31).
// Per k16-step: 4x ldmatrix.x4 (A hi/lo, 2 m-tiles) + 8x ldmatrix.x2 (B hi/lo)
// + 24 HMMA (x3 scheme: hi*hi + hi*lo + lo*hi).
#define B_STRIDE 264                           // bf16 elems per B row (k), padded
#define A_STRIDE 72                            // bf16 elems per A row (k64 chunk), padded
#define SB_LO   (128 * B_STRIDE * 2)           // 67584
#define SA_OFF  (2 * 128 * B_STRIDE * 2)       // 135168
#define A_MAT   (128 * A_STRIDE * 2)           // 18432
#define A_BUF   (2 * A_MAT)                    // 36864 (hi+lo)
#define TC_SMEM (SA_OFF + 2 * A_BUF)           // 208896
#define GTILE   128

__global__ void __launch_bounds__(512)
sage_gemm_tc(const float* __restrict__ A0,     // mean (k 0..127)
             const float* __restrict__ A1,     // feat (k 128..255)
             const float* __restrict__ Wl,
             const float* __restrict__ Wr,
             const float* __restrict__ bias,
             float* __restrict__ out,
             int nnodes, int relu, int ntiles) {
    extern __shared__ char smem[];
    uint32_t sbase = smem_u32(smem);
    __nv_bfloat16* sb_hi = reinterpret_cast<__nv_bfloat16*>(smem);
    __nv_bfloat16* sb_lo = reinterpret_cast<__nv_bfloat16*>(smem + SB_LO);

    int tid = threadIdx.x;
    int lane = tid & 31;
    int warp = tid >> 5;

    // ---- convert W = [Wl|Wr] to bf16 hi/lo in smem (once per CTA) ----
    for (int idx = tid; idx < 128 * 256; idx += 512) {
        int j = idx >> 8;
        int k = idx & 255;
        float w = (k < 128) ? Wl[j * 128 + k] : Wr[j * 128 + (k - 128)];
        __nv_bfloat16 h = __float2bfloat16(w);
        float lo = w - __bfloat162float(h);
        sb_hi[j * B_STRIDE + k] = h;
        sb_lo[j * B_STRIDE + k] = __float2bfloat16(lo);
    }

    // ---- warp tile roles ----
    int mi2 = warp & 3;            // rows mi2*32 .. +31 (2 m16 tiles)
    int ng = warp >> 2;            // cols ng*32 .. +31 (4 n8 tiles)
    int g = lane >> 2, t4 = lane & 3;

    // bias registers (j layout invariant across tiles)
    float breg[4][2];
#pragma unroll
    for (int nt = 0; nt < 4; ++nt) {
        int j = ng * 32 + nt * 8 + t4 * 2;
        breg[nt][0] = bias[j];
        breg[nt][1] = bias[j + 1];
    }

    // ldmatrix per-thread address components
    int arow = lane & 15, ahalf = (lane >> 4) & 1;
    int brow = lane & 7, bhalf = (lane >> 3) & 1;
    uint32_t a_off0 = (uint32_t)((mi2 * 32 + arow) * (A_STRIDE * 2) + ahalf * 16);
    uint32_t a_off1 = (uint32_t)((mi2 * 32 + 16 + arow) * (A_STRIDE * 2) + ahalf * 16);
    uint32_t b_base = sbase + (uint32_t)((ng * 32 + brow) * (B_STRIDE * 2) + bhalf * 16);

    // staging role: thread stages 16 k-values of one node per 64-k chunk
    int st_node = tid >> 2;        // 0..127
    int st_q = tid & 3;            // 0..3 -> k offsets q*16..+15

    for (int tile = blockIdx.x; tile < ntiles; tile += gridDim.x) {
        int base_node = tile * GTILE;
        int st_gnode = base_node + st_node;
        if (st_gnode >= nnodes) st_gnode = nnodes - 1;
        const float4* a0p = reinterpret_cast<const float4*>(
            A0 + (size_t)st_gnode * DFEAT + st_q * 16);
        const float4* a1p = reinterpret_cast<const float4*>(
            A1 + (size_t)st_gnode * DFEAT + st_q * 16);

        // prefetch chunk 0 (mean, k 0..63)
        float4 p0 = a0p[0], p1 = a0p[1], p2 = a0p[2], p3 = a0p[3];

        float acc[2][4][4];
#pragma unroll
        for (int mm = 0; mm < 2; ++mm)
#pragma unroll
            for (int nt = 0; nt < 4; ++nt)
#pragma unroll
                for (int q = 0; q < 4; ++q) acc[mm][nt][q] = 0.f;

        for (int c = 0; c < 4; ++c) {
            // ---- stage chunk c as bf16 hi/lo ----
            char* ab = smem + SA_OFF + (c & 1) * A_BUF;
            uint32_t* ah32 = reinterpret_cast<uint32_t*>(
                ab + st_node * (A_STRIDE * 2) + st_q * 32);
            uint32_t* al32 = reinterpret_cast<uint32_t*>(
                ab + A_MAT + st_node * (A_STRIDE * 2) + st_q * 32);
            float f[16] = {p0.x, p0.y, p0.z, p0.w, p1.x, p1.y, p1.z, p1.w,
                           p2.x, p2.y, p2.z, p2.w, p3.x, p3.y, p3.z, p3.w};
#pragma unroll
            for (int i = 0; i < 8; ++i) {
                float x0 = f[2 * i], x1 = f[2 * i + 1];
                __nv_bfloat16 h0 = __float2bfloat16(x0);
                __nv_bfloat16 h1 = __float2bfloat16(x1);
                __nv_bfloat16 l0 = __float2bfloat16(x0 - __bfloat162float(h0));
                __nv_bfloat16 l1 = __float2bfloat16(x1 - __bfloat162float(h1));
                __nv_bfloat162 hv; hv.x = h0; hv.y = h1;
                __nv_bfloat162 lv; lv.x = l0; lv.y = l1;
                ah32[i] = *reinterpret_cast<uint32_t*>(&hv);
                al32[i] = *reinterpret_cast<uint32_t*>(&lv);
            }

            // prefetch chunk c+1
            if (c + 1 < 4) {
                const float4* ap = (c + 1 < 2) ? a0p : a1p;
                int qoff = ((c + 1) & 1) * 16;   // 64 floats = 16 float4s
                p0 = ap[qoff + 0]; p1 = ap[qoff + 1];
                p2 = ap[qoff + 2]; p3 = ap[qoff + 3];
            }
            __syncthreads();

            // ---- compute 4 k16-steps of chunk c ----
            uint32_t abuf = sbase + SA_OFF + (c & 1) * A_BUF;
            uint32_t kb_b = (uint32_t)(c * 128);   // chunk byte offset in B k-dim
#pragma unroll
            for (int ks = 0; ks < 4; ++ks) {
                uint32_t ak = (uint32_t)(ks * 32);
                uint32_t ah0[4], al0[4], ah1[4], al1[4];
                LDMX4(ah0, abuf + a_off0 + ak);
                LDMX4(al0, abuf + A_MAT + a_off0 + ak);
                LDMX4(ah1, abuf + a_off1 + ak);
                LDMX4(al1, abuf + A_MAT + a_off1 + ak);
                uint32_t kbyte = kb_b + (uint32_t)(ks * 32);
#pragma unroll
                for (int nt = 0; nt < 4; ++nt) {
                    uint32_t ba = b_base + (uint32_t)(nt * 8 * B_STRIDE * 2) + kbyte;
                    uint32_t bh0, bh1, bl0, bl1;
                    LDMX2(bh0, bh1, ba);
                    LDMX2(bl0, bl1, ba + SB_LO);
                    MMA4(acc[0][nt], ah0, bh0, bh1);
                    MMA4(acc[0][nt], ah0, bl0, bl1);
                    MMA4(acc[0][nt], al0, bh0, bh1);
                    MMA4(acc[1][nt], ah1, bh0, bh1);
                    MMA4(acc[1][nt], ah1, bl0, bl1);
                    MMA4(acc[1][nt], al1, bh0, bh1);
                }
            }
        }

        // ---- epilogue: bias + relu + store ----
#pragma unroll
        for (int mm = 0; mm < 2; ++mm) {
            int ra = base_node + mi2 * 32 + mm * 16 + g;
            int rb = ra + 8;
#pragma unroll
            for (int nt = 0; nt < 4; ++nt) {
                int j = ng * 32 + nt * 8 + t4 * 2;
                float2 o0, o1;
                o0.x = acc[mm][nt][0] + breg[nt][0];
                o0.y = acc[mm][nt][1] + breg[nt][1];
                o1.x = acc[mm][nt][2] + breg[nt][0];
                o1.y = acc[mm][nt][3] + breg[nt][1];
                if (relu) {
                    o0.x = fmaxf(o0.x, 0.f); o0.y = fmaxf(o0.y, 0.f);
                    o1.x = fmaxf(o1.x, 0.f); o1.y = fmaxf(o1.y, 0.f);
                }
                if (ra < nnodes)
                    *reinterpret_cast<float2*>(out + (size_t)ra * DFEAT + j) = o0;
                if (rb < nnodes)
                    *reinterpret_cast<float2*>(out + (size_t)rb * DFEAT + j) = o1;
            }
        }
        __syncthreads();   // A bufs safe before next tile's staging
    }
}

// ---------------- launch ----------------------------------------------------
extern "C" void kernel_launch(void* const* d_in, const int* in_sizes, int n_in,
                              void* d_out, int out_size) {
    const float* x   = (const float*)d_in[0];
    const int*   ew  = (const int*)d_in[1];
    const float* Wl1 = (const float*)d_in[2];
    const float* bl1 = (const float*)d_in[3];
    const float* Wr1 = (const float*)d_in[4];
    const float* Wl2 = (const float*)d_in[5];
    const float* bl2 = (const float*)d_in[6];
    const float* Wr2 = (const float*)d_in[7];
    float*       out = (float*)d_out;

    int n = in_sizes[0] / DFEAT;      // 100000
    int e = in_sizes[1] / 2;          // 1600000

    void *p_mean_v, *p_h_v, *p_cursor_v;
    cudaGetSymbolAddress(&p_mean_v, g_mean);
    cudaGetSymbolAddress(&p_h_v, g_h);
    cudaGetSymbolAddress(&p_cursor_v, g_cursor);
    float* p_mean = (float*)p_mean_v;
    float* p_h = (float*)p_h_v;
    int* p_cursor = (int*)p_cursor_v;

    cudaFuncSetAttribute(sage_gemm_tc,
                         cudaFuncAttributeMaxDynamicSharedMemorySize, TC_SMEM);

    int zb = (n + 255) / 256;
    int eb = (e + 255) / 256;
    int ab = (n + 7) / 8;
    int sb = (n + SCAN_BLK - 1) / SCAN_BLK;
    int ntiles = (n + GTILE - 1) / GTILE;

    // ---- CSR build ----
    detect_kernel<<<1, 1>>>(ew);
    zero_int_kernel<<<zb, 256>>>(p_cursor, n);
    convert_count_kernel<<<eb, 256>>>(ew, e, n);
    scan_partial_kernel<<<sb, SCAN_BLK>>>(n);
    scan_bsums_kernel<<<1, SCAN_BLK>>>(sb, n);
    scan_add_kernel<<<sb, SCAN_BLK>>>(n);
    fill_csr_kernel<<<eb, 256>>>(e);

    // ---- layer 1 ----
    agg_mean_kernel<<<ab, 256>>>(x, n);
    sage_gemm_tc<<<148, 512, TC_SMEM>>>(p_mean, x, Wl1, Wr1, bl1, p_h, n, 1, ntiles);

    // ---- layer 2 ----
    agg_mean_kernel<<<ab, 256>>>(p_h, n);
    sage_gemm_tc<<<148, 512, TC_SMEM>>>(p_mean, p_h, Wl2, Wr2, bl2, out, n, 0, ntiles);
}